// round 7
// baseline (speedup 1.0000x reference)
#include <cuda_runtime.h>
#include <math.h>

#define B_DIM 64
#define D_DIM 65536
#define S_SL  8
#define NTH   512
#define SLICE (D_DIM / S_SL)               // 8192 elements
#define QPT   (SLICE / 4 / NTH)            // 4 quads per thread
#define CAP   2048
#define BIAS  6000                         // bin = (key>>19) - BIAS
#define SAFE_BIN 128                       // bin 128 <-> x = 1.0
#define NB    128                          // tracked bins (128..255)

// ---- __device__ scratch (allocation-free; fully overwritten / self-resetting) ----
__device__ unsigned g_bins32[B_DIM * D_DIM / 4];   // 4MB: 4 packed u8 bins (0 if <128)
__device__ unsigned g_hist[B_DIM * S_SL * NB];
__device__ float    g_hsum[B_DIM * S_SL * NB];
__device__ float    g_sl_loc[B_DIM * S_SL];
__device__ float    g_sl_bce[B_DIM * S_SL];
__device__ int      g_sl_pos[B_DIM * S_SL];
__device__ float    g_row_loc[B_DIM];
__device__ float    g_row_conf[B_DIM];
__device__ int      g_row_pos[B_DIM];
__device__ int      g_row_sel[B_DIM];
__device__ int      g_row_ctr[B_DIM];              // per-row finisher counters (self-reset)
__device__ int      g_ctr;                         // global finisher counter (self-reset)

__device__ __forceinline__ float softplus_f(float x) {
    return fmaxf(x, 0.0f) + log1pf(expf(-fabsf(x)));
}
__device__ __forceinline__ float sl1f(float d) {
    float ad = fabsf(d);
    return (ad < 1.0f) ? 0.5f * d * d : (ad - 0.5f);
}
__device__ __forceinline__ unsigned key_of(float x) {
    unsigned u = __float_as_uint(x);
    return (u & 0x80000000u) ? ~u : (u | 0x80000000u);
}
__device__ __forceinline__ float val_of_key(unsigned k) {
    unsigned u = (k & 0x80000000u) ? (k & 0x7FFFFFFFu) : ~k;
    return __uint_as_float(u);
}
__device__ __forceinline__ int bin_of(unsigned key) {
    return min(255, max(0, (int)(key >> 19) - BIAS));
}

template<int NWARP>
__device__ __forceinline__ float blk_sum(float v, float* red, int t) {
    #pragma unroll
    for (int o = 16; o > 0; o >>= 1) v += __shfl_down_sync(0xFFFFFFFFu, v, o);
    if ((t & 31) == 0) red[t >> 5] = v;
    __syncthreads();
    if (t < 32) {
        float w = (t < NWARP) ? red[t] : 0.0f;
        #pragma unroll
        for (int o = 16; o > 0; o >>= 1) w += __shfl_down_sync(0xFFFFFFFFu, w, o);
        if (t == 0) red[0] = w;
    }
    __syncthreads();
    float r = red[0];
    __syncthreads();
    return r;
}

// Warp-cooperative descending select over NBINS bins (lanes 0..31).
template<int NBINS>
__device__ __forceinline__ int warp_select(const unsigned* h, int k, int lane, int* rem_out) {
    const int PER = NBINS / 32;
    int s = 0;
    #pragma unroll
    for (int m = 0; m < PER; m++) s += (int)h[NBINS - 1 - lane * PER - m];
    int inc = s;
    #pragma unroll
    for (int o = 1; o < 32; o <<= 1) {
        int v = __shfl_up_sync(0xFFFFFFFFu, inc, o);
        if (lane >= o) inc += v;
    }
    int pre = inc - s;
    unsigned m = __ballot_sync(0xFFFFFFFFu, (pre < k) && (pre + s >= k));
    int chosen = __ffs(m) - 1;
    int bin = 0, rem = 0;
    if (lane == chosen) {
        int acc = pre, hi = NBINS - 1 - lane * PER;
        #pragma unroll
        for (int b = 0; b < PER; b++) {
            int c = (int)h[hi - b];
            if (acc + c >= k) { bin = hi - b; rem = k - acc; break; }
            acc += c;
        }
    }
    bin = __shfl_sync(0xFFFFFFFFu, bin, chosen);
    rem = __shfl_sync(0xFFFFFFFFu, rem, chosen);
    *rem_out = rem;
    return bin;
}

// ======================= ONE fused kernel =======================
__global__ void __launch_bounds__(NTH) mbl_fused(
    const float4* __restrict__ loc_data,
    const float*  __restrict__ conf,
    const float4* __restrict__ loc_t,
    const int*    __restrict__ ct,
    float* __restrict__ out)
{
    __shared__ unsigned wh[16][NB];   // 8KB warp-private counts (pass-1)
    __shared__ float    ws[16][NB];   // 8KB warp-private sp-sums (pass-1)
    __shared__ float    red[32];
    // select-phase storage
    __shared__ unsigned h[NB];
    __shared__ float    hs[NB];
    __shared__ unsigned rh[256];
    __shared__ unsigned list[CAP];    // 8KB
    __shared__ int      sh_ib, sh_rem, sh_nlist, sh_bin2, sh_rem2, sh_tot;
    __shared__ int      sh_fin, sh_last;

    const int t = threadIdx.x, w = t >> 5;
    const int row = blockIdx.x / S_SL, sl = blockIdx.x % S_SL;

    for (int i = t; i < 16 * NB; i += NTH) { ((unsigned*)wh)[i] = 0; ((float*)ws)[i] = 0.0f; }
    __syncthreads();

    // ---------------- Pass-1 slice: stats + bin bytes + gated histogram ----------------
    const float4* conf4 = reinterpret_cast<const float4*>(conf);
    const int4*   ct4   = reinterpret_cast<const int4*>(ct);
    const int qr0 = row * (D_DIM / 4) + sl * (SLICE / 4);

    float npos = 0.0f, pb = 0.0f, ls = 0.0f;
    #pragma unroll
    for (int j = 0; j < QPT; j++) {
        int qg = qr0 + t + j * NTH;
        float4 x = conf4[qg];
        int4   c = ct4[qg];
        float xs[4] = {x.x, x.y, x.z, x.w};
        int   cs[4] = {c.x, c.y, c.z, c.w};
        unsigned packed = 0u;
        #pragma unroll
        for (int cc = 0; cc < 4; cc++) {
            size_t e = 4 * (size_t)qg + cc;
            if (cs[cc] > 0) {
                npos += 1.0f; pb += softplus_f(-xs[cc]);
                float4 a = loc_data[e], b = loc_t[e];
                ls += sl1f(a.x - b.x) + sl1f(a.y - b.y) + sl1f(a.z - b.z) + sl1f(a.w - b.w);
            } else {
                int bin = bin_of(key_of(xs[cc]));
                if (bin >= SAFE_BIN) {              // ~6% of elements
                    packed |= (unsigned)bin << (8 * cc);
                    atomicAdd(&wh[w][bin - SAFE_BIN], 1u);
                    atomicAdd(&ws[w][bin - SAFE_BIN], softplus_f(xs[cc]));
                }
            }
        }
        g_bins32[qg] = packed;
    }
    __syncthreads();

    if (t < NB) {
        unsigned s = 0;
        #pragma unroll
        for (int m = 0; m < 16; m++) s += wh[m][t];
        g_hist[blockIdx.x * NB + t] = s;
    } else if (t < 2 * NB) {
        int b = t - NB;
        float s = 0.0f;
        #pragma unroll
        for (int m = 0; m < 16; m++) s += ws[m][b];
        g_hsum[blockIdx.x * NB + b] = s;
    }

    float npos_r = blk_sum<16>(npos, red, t);
    float ls_r   = blk_sum<16>(ls,   red, t);
    float pb_r   = blk_sum<16>(pb,   red, t);
    if (t == 0) {
        g_sl_pos[blockIdx.x] = (int)npos_r;
        g_sl_loc[blockIdx.x] = ls_r;
        g_sl_bce[blockIdx.x] = pb_r;
    }
    __threadfence();
    __syncthreads();

    // ---------------- Row-finisher election ----------------
    if (t == 0) {
        int v = atomicAdd(&g_row_ctr[row], 1);
        sh_fin = (v == S_SL - 1) ? 1 : 0;
        if (sh_fin) g_row_ctr[row] = 0;          // self-reset for next replay
    }
    __syncthreads();
    if (!sh_fin) return;
    __threadfence();                             // acquire other slices' writes
    __syncthreads();

    // ---------------- Per-row select (this CTA only) ----------------
    int  npos_row; float pb_row, ls_row;
    if (t < NB) {
        unsigned s = 0;
        #pragma unroll
        for (int m = 0; m < S_SL; m++) s += g_hist[(row * S_SL + m) * NB + t];
        h[t] = s;
    } else if (t < 2 * NB) {
        int b = t - NB;
        float s = 0.0f;
        #pragma unroll
        for (int m = 0; m < S_SL; m++) s += g_hsum[(row * S_SL + m) * NB + b];
        hs[b] = s;
    }
    {
        int np = 0; float pbs = 0.0f, lss = 0.0f;
        #pragma unroll
        for (int m = 0; m < S_SL; m++) {
            np  += g_sl_pos[row * S_SL + m];
            pbs += g_sl_bce[row * S_SL + m];
            lss += g_sl_loc[row * S_SL + m];
        }
        npos_row = np; pb_row = pbs; ls_row = lss;
    }
    if (t == 0) sh_nlist = 0;
    __syncthreads();
    const int k = min(3 * npos_row, D_DIM);

    if (t < 32) {
        int s = 0;
        #pragma unroll
        for (int m = 0; m < 4; m++) s += (int)h[t * 4 + m];
        #pragma unroll
        for (int o = 16; o > 0; o >>= 1) s += __shfl_down_sync(0xFFFFFFFFu, s, o);
        if (t == 0) sh_tot = s;
        __syncwarp();
        int tot = __shfl_sync(0xFFFFFFFFu, sh_tot, 0);
        if (k > 0 && tot >= k) {
            int rem; int ib = warp_select<NB>(h, k, t, &rem);
            if (t == 0) { sh_ib = ib; sh_rem = rem; }
        } else if (t == 0) sh_ib = -1;
    }
    __syncthreads();
    const int ib = sh_ib;
    const int b8 = SAFE_BIN + ib;
    const bool fast = (k > 0) && (ib >= 0) && (ib < NB - 1);

    float csum = 0.0f;
    unsigned T = 0u; int req = 0;

    if (fast) {
        if (t < NB && t > ib) csum += hs[t];     // strict part from per-bin sums

        // scan this row's 64KB of packed bins; gather boundary logits
        const uint4* bp = reinterpret_cast<const uint4*>(g_bins32 + (size_t)row * (D_DIM / 4));
        const unsigned rep = (unsigned)b8 * 0x01010101u;
        #pragma unroll
        for (int jj = 0; jj < D_DIM / 16 / NTH; jj++) {     // 8 iterations
            int i4 = t + jj * NTH;
            uint4 wv = bp[i4];
            unsigned wd[4] = {wv.x, wv.y, wv.z, wv.w};
            #pragma unroll
            for (int wi = 0; wi < 4; wi++) {
                unsigned xx = wd[wi] ^ rep;
                if ((xx - 0x01010101u) & ~xx & 0x80808080u) {
                    #pragma unroll
                    for (int bi = 0; bi < 4; bi++) {
                        if (((wd[wi] >> (8 * bi)) & 255u) == (unsigned)b8) {
                            int idx = i4 * 16 + wi * 4 + bi;
                            int p = atomicAdd(&sh_nlist, 1);
                            if (p < CAP) list[p] = key_of(conf[(size_t)row * D_DIM + idx]);
                        }
                    }
                }
            }
        }
    }
    __syncthreads();
    const int nlist = sh_nlist;

    if (fast && nlist <= CAP) {
        int rem = sh_rem;
        unsigned c1, c2, c3;
        if (t < 256) rh[t] = 0;
        __syncthreads();
        for (int p = t; p < nlist; p += NTH) atomicAdd(&rh[(list[p] >> 11) & 255u], 1u);
        __syncthreads();
        if (t < 32) { int r; int b = warp_select<256>(rh, rem, t, &r); if (t == 0) { sh_bin2 = b; sh_rem2 = r; } }
        __syncthreads();
        c1 = (unsigned)sh_bin2; rem = sh_rem2;
        __syncthreads();
        if (t < 256) rh[t] = 0;
        __syncthreads();
        for (int p = t; p < nlist; p += NTH) {
            unsigned kk = list[p];
            if (((kk >> 11) & 255u) == c1) atomicAdd(&rh[(kk >> 3) & 255u], 1u);
        }
        __syncthreads();
        if (t < 32) { int r; int b = warp_select<256>(rh, rem, t, &r); if (t == 0) { sh_bin2 = b; sh_rem2 = r; } }
        __syncthreads();
        c2 = (unsigned)sh_bin2; rem = sh_rem2;
        __syncthreads();
        if (t < 256) rh[t] = 0;
        __syncthreads();
        for (int p = t; p < nlist; p += NTH) {
            unsigned kk = list[p];
            if (((kk >> 11) & 255u) == c1 && ((kk >> 3) & 255u) == c2)
                atomicAdd(&rh[kk & 7u], 1u);
        }
        __syncthreads();
        if (t < 32) { int r; int b = warp_select<256>(rh, rem, t, &r); if (t == 0) { sh_bin2 = b; sh_rem2 = r; } }
        __syncthreads();
        c3 = (unsigned)sh_bin2; req = sh_rem2;

        T = ((unsigned)(b8 + BIAS) << 19) | (c1 << 11) | (c2 << 3) | c3;
        for (int p = t; p < nlist; p += NTH) {
            unsigned kk = list[p];
            if (kk > T) csum += softplus_f(val_of_key(kk));
        }
    } else if (k > 0) {
        // exact fallback: radix select recomputing keys from conf/ct (rare)
        csum = 0.0f;
        const size_t r0 = (size_t)row * D_DIM;
        unsigned prefix = 0u; int rem = k;
        for (int lvl = 0; lvl < 4; lvl++) {
            if (t < 256) rh[t] = 0;
            __syncthreads();
            for (int j = 0; j < D_DIM / NTH; j++) {
                size_t e = r0 + t + (size_t)j * NTH;
                if (ct[e] <= 0) {
                    unsigned kk = key_of(conf[e]);
                    if (lvl == 0 || (kk >> (32 - 8 * lvl)) == prefix)
                        atomicAdd(&rh[(kk >> (24 - 8 * lvl)) & 255u], 1u);
                }
            }
            __syncthreads();
            if (t < 32) { int r; int b = warp_select<256>(rh, rem, t, &r); if (t == 0) { sh_bin2 = b; sh_rem2 = r; } }
            __syncthreads();
            prefix = (prefix << 8) | (unsigned)sh_bin2;
            rem = sh_rem2;
            __syncthreads();
        }
        T = prefix; req = rem;
        for (int j = 0; j < D_DIM / NTH; j++) {
            size_t e = r0 + t + (size_t)j * NTH;
            if (ct[e] <= 0) {
                float xv = conf[e];
                if (key_of(xv) > T) csum += softplus_f(xv);
            }
        }
    }
    __syncthreads();

    float csum_row = blk_sum<16>(csum, red, t);
    if (t == 0) {
        float tv = (req > 0) ? softplus_f(val_of_key(T)) : 0.0f;
        g_row_conf[row] = pb_row + csum_row + (float)req * tv;
        g_row_loc[row]  = ls_row;
        g_row_pos[row]  = npos_row;
        g_row_sel[row]  = npos_row + k;
        __threadfence();
        int v = atomicAdd(&g_ctr, 1);
        sh_last = (v == B_DIM - 1) ? 1 : 0;
        if (sh_last) g_ctr = 0;                  // self-reset
    }
    __syncthreads();
    if (!sh_last) return;
    __threadfence();
    __syncthreads();

    // ---------------- Global finisher: cross-row reduction ----------------
    if (t < 64) {
        float lc = g_row_loc[t], cf = g_row_conf[t];
        float ps = (float)g_row_pos[t], slv = (float)g_row_sel[t];
        #pragma unroll
        for (int o = 16; o > 0; o >>= 1) {
            lc  += __shfl_down_sync(0xFFFFFFFFu, lc,  o);
            cf  += __shfl_down_sync(0xFFFFFFFFu, cf,  o);
            ps  += __shfl_down_sync(0xFFFFFFFFu, ps,  o);
            slv += __shfl_down_sync(0xFFFFFFFFu, slv, o);
        }
        if ((t & 31) == 0) {
            red[(t >> 5) * 4 + 0] = lc; red[(t >> 5) * 4 + 1] = cf;
            red[(t >> 5) * 4 + 2] = ps; red[(t >> 5) * 4 + 3] = slv;
        }
    }
    __syncthreads();
    if (t == 0) {
        float lc = red[0] + red[4], cf = red[1] + red[5];
        float ps = red[2] + red[6], slv = red[3] + red[7];
        out[0] = lc / (4.0f * ps) / ps;
        out[1] = cf / slv / ps;
    }
}

extern "C" void kernel_launch(void* const* d_in, const int* in_sizes, int n_in,
                              void* d_out, int out_size)
{
    const float4* loc_data  = nullptr;
    const float4* loc_tgt   = nullptr;
    const float*  conf_data = nullptr;
    const int*    conf_tgt  = nullptr;
    for (int i = 0; i < n_in; i++) {
        if (in_sizes[i] == B_DIM * D_DIM * 4) {
            if (!loc_data) loc_data = (const float4*)d_in[i];
            else           loc_tgt  = (const float4*)d_in[i];
        } else {
            if (!conf_data) conf_data = (const float*)d_in[i];
            else            conf_tgt  = (const int*)d_in[i];
        }
    }

    mbl_fused<<<B_DIM * S_SL, NTH>>>(loc_data, conf_data, loc_tgt, conf_tgt,
                                     (float*)d_out);
}